// round 17
// baseline (speedup 1.0000x reference)
#include <cuda_runtime.h>
#include <cuda_bf16.h>
#include <stdint.h>
#include <math.h>

// Problem constants
#define N_TOK 16384          // B*T
#define G     2
#define M     1024
#define D     256
#define GD    512            // G*D
#define GM    2048           // G*M
#define KCAT  1536           // 6 * D (bf16x3 split, 6 products via K-concat)

// Output layout (concatenated, float32)
#define OFF_Q    0
#define OFF_CODE 8388608
#define OFF_PROB 8388610
#define OFF_IND  8388612
#define OFF_LOSS 8421380

// -------- device scratch --------
__device__ float          g_logits[33554432];          // [N_TOK, G, M] 134 MB
__device__ float          g_sqe[GM];
__device__ float          g_avgprob[GM];
__device__ float          g_hardcnt[GM];
__device__ double         g_commit;
__device__ __nv_bfloat16  g_acat[2 * 16384 * KCAT];    // [g][n][1536] 100 MB
__device__ __nv_bfloat16  g_bcat[2 * 1024 * KCAT];     // [g][m][1536] 6 MB

// ======================================================================
// PTX helpers (all baseline ISA: sm_80-era, safe at compute_103)
// ======================================================================
__device__ __forceinline__ uint32_t smem_u32(const void* p) {
    uint32_t a;
    asm("{ .reg .u64 t; cvta.to.shared.u64 t, %1; cvt.u32.u64 %0, t; }"
        : "=r"(a) : "l"(p));
    return a;
}

#define CP16(dst, src) \
    asm volatile("cp.async.cg.shared.global [%0], [%1], 16;" :: "r"(dst), "l"(src))
#define CP_COMMIT() asm volatile("cp.async.commit_group;" ::: "memory")
#define CP_WAIT1()  asm volatile("cp.async.wait_group 1;" ::: "memory")
#define CP_WAIT0()  asm volatile("cp.async.wait_group 0;" ::: "memory")

#define LDSM4(r0, r1, r2, r3, addr) \
    asm volatile("ldmatrix.sync.aligned.m8n8.x4.shared.b16 {%0,%1,%2,%3}, [%4];" \
                 : "=r"(r0), "=r"(r1), "=r"(r2), "=r"(r3) : "r"(addr))

__device__ __forceinline__ void mma16816(float* d, const uint32_t* a,
                                         const uint32_t* b) {
    asm volatile(
        "mma.sync.aligned.m16n8k16.row.col.f32.bf16.bf16.f32 "
        "{%0,%1,%2,%3},{%4,%5,%6,%7},{%8,%9},{%0,%1,%2,%3};"
        : "+f"(d[0]), "+f"(d[1]), "+f"(d[2]), "+f"(d[3])
        : "r"(a[0]), "r"(a[1]), "r"(a[2]), "r"(a[3]), "r"(b[0]), "r"(b[1]));
}

// ======================================================================
// K0: sq_e + zero accumulators
// ======================================================================
__global__ void k_prep(const float* __restrict__ emb) {
    int row  = blockIdx.x * 8 + (threadIdx.x >> 5);
    int lane = threadIdx.x & 31;
    if (row < GM) {
        const float* e = emb + (size_t)row * D;
        float s = 0.f;
        #pragma unroll
        for (int d = lane; d < D; d += 32) { float v = e[d]; s = fmaf(v, v, s); }
        #pragma unroll
        for (int o = 16; o > 0; o >>= 1) s += __shfl_xor_sync(0xffffffffu, s, o);
        if (lane == 0) {
            g_sqe[row] = s; g_avgprob[row] = 0.f; g_hardcnt[row] = 0.f;
        }
    }
    if (blockIdx.x == 0 && threadIdx.x == 0) g_commit = 0.0;
}

// ======================================================================
// bf16x3 split of x into A_cat = [a1|a1|a1|a2|a2|a3]
// ======================================================================
__global__ void __launch_bounds__(256) k_convert_x(const float* __restrict__ x) {
    int idx = blockIdx.x * 256 + threadIdx.x;       // pair index, 2 floats each
    int n  = idx >> 8;
    int c2 = idx & 255;
    int g  = c2 >> 7;
    int d  = (c2 & 127) << 1;
    float2 v = *(const float2*)(x + (size_t)n * GD + g * D + d);

    __nv_bfloat16 a1x = __float2bfloat16(v.x);
    float r = v.x - __bfloat162float(a1x);
    __nv_bfloat16 a2x = __float2bfloat16(r);
    __nv_bfloat16 a3x = __float2bfloat16(r - __bfloat162float(a2x));
    __nv_bfloat16 a1y = __float2bfloat16(v.y);
    r = v.y - __bfloat162float(a1y);
    __nv_bfloat16 a2y = __float2bfloat16(r);
    __nv_bfloat16 a3y = __float2bfloat16(r - __bfloat162float(a2y));

    __nv_bfloat162 p1; p1.x = a1x; p1.y = a1y;
    __nv_bfloat162 p2; p2.x = a2x; p2.y = a2y;
    __nv_bfloat162 p3; p3.x = a3x; p3.y = a3y;

    __nv_bfloat16* base = g_acat + ((size_t)(g * 16384 + n) * KCAT + d);
    *(__nv_bfloat162*)(base +    0) = p1;
    *(__nv_bfloat162*)(base +  256) = p1;
    *(__nv_bfloat162*)(base +  512) = p1;
    *(__nv_bfloat162*)(base +  768) = p2;
    *(__nv_bfloat162*)(base + 1024) = p2;
    *(__nv_bfloat162*)(base + 1280) = p3;
}

// B_cat = [b1|b2|b3|b1|b2|b1]
__global__ void __launch_bounds__(256) k_convert_e(const float* __restrict__ emb) {
    int idx = blockIdx.x * 256 + threadIdx.x;       // pair index
    int row = idx >> 7;                             // g*1024 + m
    int d   = (idx & 127) << 1;
    float2 v = *(const float2*)(emb + (size_t)row * D + d);

    __nv_bfloat16 b1x = __float2bfloat16(v.x);
    float r = v.x - __bfloat162float(b1x);
    __nv_bfloat16 b2x = __float2bfloat16(r);
    __nv_bfloat16 b3x = __float2bfloat16(r - __bfloat162float(b2x));
    __nv_bfloat16 b1y = __float2bfloat16(v.y);
    r = v.y - __bfloat162float(b1y);
    __nv_bfloat16 b2y = __float2bfloat16(r);
    __nv_bfloat16 b3y = __float2bfloat16(r - __bfloat162float(b2y));

    __nv_bfloat162 p1; p1.x = b1x; p1.y = b1y;
    __nv_bfloat162 p2; p2.x = b2x; p2.y = b2y;
    __nv_bfloat162 p3; p3.x = b3x; p3.y = b3y;

    __nv_bfloat16* base = g_bcat + ((size_t)row * KCAT + d);
    *(__nv_bfloat162*)(base +    0) = p1;
    *(__nv_bfloat162*)(base +  256) = p2;
    *(__nv_bfloat162*)(base +  512) = p3;
    *(__nv_bfloat162*)(base +  768) = p1;
    *(__nv_bfloat162*)(base + 1024) = p2;
    *(__nv_bfloat162*)(base + 1280) = p1;
}

// ======================================================================
// K1: classic HMMA GEMM (mma.sync m16n8k16 bf16, fp32 accum).
// Block tile 128 tokens x 128 codes, BK=64, cp.async double buffer.
// 8 warps in 2x4: each warp 64 tokens x 32 codes.
// grid (8 code-tiles, 128 token-tiles, 2 g) x 256 threads
// ======================================================================
#define NCHUNK 24                      // K = 1536 = 24 * 64
#define SMEM_GEMM (65536 + 128)

__global__ void __launch_bounds__(256, 1) k_gemm_mma() {
    extern __shared__ char dsm[];
    uint32_t raw  = smem_u32(dsm);
    uint32_t base = (raw + 127u) & ~127u;
    uint32_t sA[2] = { base,          base + 16384u };
    uint32_t sB[2] = { base + 32768u, base + 49152u };

    int tid  = threadIdx.x;
    int wid  = tid >> 5, lane = tid & 31;
    int g    = blockIdx.z;
    int m0   = blockIdx.x * 128;       // codes
    int n0   = blockIdx.y * 128;       // tokens

    const char* Abase = (const char*)(g_acat + (size_t)(g * 16384 + n0) * KCAT);
    const char* Bbase = (const char*)(g_bcat + (size_t)(g * 1024  + m0) * KCAT);

    // loader mapping: thread -> (row, 64B half), 4x cp.async 16B each
    int lr = tid >> 1;
    int lh = (tid & 1) * 64;
    uint32_t lsw[4];
    #pragma unroll
    for (int j = 0; j < 4; j++)
        lsw[j] = (uint32_t)lr * 128u + (uint32_t)((lh + j * 16) ^ ((lr & 7) << 4));
    const char* Arow = Abase + (size_t)lr * (KCAT * 2) + lh;
    const char* Brow = Bbase + (size_t)lr * (KCAT * 2) + lh;

    float acc[4][4][4];
    #pragma unroll
    for (int i = 0; i < 4; i++)
        #pragma unroll
        for (int j = 0; j < 4; j++)
            #pragma unroll
            for (int q = 0; q < 4; q++) acc[i][j][q] = 0.f;

    int tb = (wid >> 2) * 64;          // warp token offset
    int cb = (wid & 3) * 32;           // warp code offset

    // precompute ldmatrix smem offsets (buffer-relative)
    // A: row = tb + im*16 + (lane & 15), byte = kk*2 + ((lane>>4)<<4)
    int arow = tb + (lane & 15);
    uint32_t abyte0 = (uint32_t)((lane >> 4) << 4);
    // B: row = cb + q*16 + (lane&7) + ((lane>>4)&1)*8, byte = kk*2 + (((lane>>3)&1)<<4)
    int brow = cb + (lane & 7) + (((lane >> 4) & 1) << 3);
    uint32_t bbyte0 = (uint32_t)(((lane >> 3) & 1) << 4);

    // preload chunk 0
    #pragma unroll
    for (int j = 0; j < 4; j++) { CP16(sA[0] + lsw[j], Arow + j * 16);
                                  CP16(sB[0] + lsw[j], Brow + j * 16); }
    CP_COMMIT();

    for (int it = 0; it < NCHUNK; it++) {
        int b = it & 1;
        if (it + 1 < NCHUNK) {
            const char* an = Arow + (it + 1) * 128;
            const char* bn = Brow + (it + 1) * 128;
            #pragma unroll
            for (int j = 0; j < 4; j++) { CP16(sA[b ^ 1] + lsw[j], an + j * 16);
                                          CP16(sB[b ^ 1] + lsw[j], bn + j * 16); }
            CP_COMMIT();
            CP_WAIT1();
        } else {
            CP_WAIT0();
        }
        __syncthreads();

        #pragma unroll
        for (int ks = 0; ks < 4; ks++) {       // kk = ks*16 elements
            uint32_t kb = (uint32_t)(ks * 32); // byte offset of k-step
            uint32_t a[4][4];
            #pragma unroll
            for (int im = 0; im < 4; im++) {
                int row = arow + im * 16;
                uint32_t byte = kb + abyte0;
                uint32_t addr = sA[b] + (uint32_t)row * 128u +
                                (byte ^ (uint32_t)((row & 7) << 4));
                LDSM4(a[im][0], a[im][1], a[im][2], a[im][3], addr);
            }
            uint32_t bf[4][2];
            #pragma unroll
            for (int q = 0; q < 2; q++) {
                int row = brow + q * 16;
                uint32_t byte = kb + bbyte0;
                uint32_t addr = sB[b] + (uint32_t)row * 128u +
                                (byte ^ (uint32_t)((row & 7) << 4));
                uint32_t r0, r1, r2, r3;
                LDSM4(r0, r1, r2, r3, addr);
                bf[q * 2 + 0][0] = r0; bf[q * 2 + 0][1] = r1;
                bf[q * 2 + 1][0] = r2; bf[q * 2 + 1][1] = r3;
            }
            #pragma unroll
            for (int im = 0; im < 4; im++)
                #pragma unroll
                for (int jn = 0; jn < 4; jn++)
                    mma16816(acc[im][jn], a[im], bf[jn]);
        }
        __syncthreads();
    }

    // epilogue: L = 2*acc - sq_e  ->  g_logits[token][g][code]
    #pragma unroll
    for (int jn = 0; jn < 4; jn++) {
        int col = m0 + cb + jn * 8 + (lane & 3) * 2;
        float sq0 = g_sqe[g * M + col];
        float sq1 = g_sqe[g * M + col + 1];
        #pragma unroll
        for (int im = 0; im < 4; im++) {
            int row = n0 + tb + im * 16 + (lane >> 2);
            float2 v0;
            v0.x = 2.0f * acc[im][jn][0] - sq0;
            v0.y = 2.0f * acc[im][jn][1] - sq1;
            *(float2*)(g_logits + ((size_t)row * G + g) * M + col) = v0;
            float2 v1;
            v1.x = 2.0f * acc[im][jn][2] - sq0;
            v1.y = 2.0f * acc[im][jn][3] - sq1;
            *(float2*)(g_logits + ((size_t)(row + 8) * G + g) * M + col) = v1;
        }
    }
}

// ======================================================================
// K2: fused per-row epilogue
// ======================================================================
#define ROWS 16

__global__ void __launch_bounds__(256) k_rows(const float* __restrict__ x,
                                              const float* __restrict__ emb,
                                              const float* __restrict__ gu,
                                              float* __restrict__ out) {
    int g    = blockIdx.y;
    int n0   = blockIdx.x * ROWS;
    int tid  = threadIdx.x;
    int lane = tid & 31, wid = tid >> 5;

    __shared__ float svL[8]; __shared__ int siL[8];
    __shared__ float svG[8]; __shared__ int siG[8];
    __shared__ float sLmax;  __shared__ int sLidx; __shared__ int sGidx;
    __shared__ float sZ;

    float accP[4]  = {0.f, 0.f, 0.f, 0.f};
    float hardC[4] = {0.f, 0.f, 0.f, 0.f};
    float commitLocal = 0.f;

    for (int r = 0; r < ROWS; r++) {
        int n = n0 + r;
        const float* Lrow = g_logits + ((size_t)n * G + g) * M;
        const float* Urow = gu       + ((size_t)n * G + g) * M;

        float Lv[4];
        float lmax = -3.4e38f; int lIdx = 0;
        float gmax = -3.4e38f; int gIdx = 0;
        #pragma unroll
        for (int j = 0; j < 4; j++) {
            int m   = tid + j * 256;
            float L = Lrow[m];
            float u = Urow[m];
            float noise = -logf(-logf(u));
            float gv = L + noise;
            Lv[j] = L;
            if (L  > lmax) { lmax = L;  lIdx = m; }
            if (gv > gmax) { gmax = gv; gIdx = m; }
        }
        #pragma unroll
        for (int o = 16; o > 0; o >>= 1) {
            float v2 = __shfl_xor_sync(0xffffffffu, lmax, o);
            int   i2 = __shfl_xor_sync(0xffffffffu, lIdx, o);
            if (v2 > lmax || (v2 == lmax && i2 < lIdx)) { lmax = v2; lIdx = i2; }
            float v3 = __shfl_xor_sync(0xffffffffu, gmax, o);
            int   i3 = __shfl_xor_sync(0xffffffffu, gIdx, o);
            if (v3 > gmax || (v3 == gmax && i3 < gIdx)) { gmax = v3; gIdx = i3; }
        }
        if (lane == 0) { svL[wid] = lmax; siL[wid] = lIdx;
                         svG[wid] = gmax; siG[wid] = gIdx; }
        __syncthreads();
        if (tid == 0) {
            float lm = svL[0]; int li = siL[0];
            float gm = svG[0]; int gi = siG[0];
            #pragma unroll
            for (int w = 1; w < 8; w++) {
                if (svL[w] > lm || (svL[w] == lm && siL[w] < li)) { lm = svL[w]; li = siL[w]; }
                if (svG[w] > gm || (svG[w] == gm && siG[w] < gi)) { gm = svG[w]; gi = siG[w]; }
            }
            sLmax = lm; sLidx = li; sGidx = gi;
        }
        __syncthreads();
        float rowMax = sLmax;
        int   hIdx   = sLidx;
        int   qIdx   = sGidx;

        float e[4];
        float ez = 0.f;
        #pragma unroll
        for (int j = 0; j < 4; j++) { e[j] = __expf(Lv[j] - rowMax); ez += e[j]; }
        #pragma unroll
        for (int o = 16; o > 0; o >>= 1) ez += __shfl_xor_sync(0xffffffffu, ez, o);
        if (lane == 0) svL[wid] = ez;
        __syncthreads();
        if (tid == 0) {
            float z = 0.f;
            #pragma unroll
            for (int w = 0; w < 8; w++) z += svL[w];
            sZ = z;
        }
        __syncthreads();
        float invZ = 1.0f / sZ;
        #pragma unroll
        for (int j = 0; j < 4; j++) accP[j] += e[j] * invZ;

        if (tid == (hIdx & 255)) hardC[hIdx >> 8] += 1.0f;

        if (tid == 0) out[OFF_IND + n * G + g] = (float)qIdx;
        const float* er = emb + ((size_t)g * M + qIdx) * D;
        float q  = er[tid];
        size_t xo = (size_t)n * GD + (size_t)g * D + tid;
        out[OFF_Q + xo] = q;
        float dd = x[xo] - q;
        commitLocal = fmaf(dd, dd, commitLocal);
    }

    #pragma unroll
    for (int j = 0; j < 4; j++) {
        atomicAdd(&g_avgprob[g * M + tid + j * 256], accP[j]);
        if (hardC[j] != 0.f) atomicAdd(&g_hardcnt[g * M + tid + j * 256], hardC[j]);
    }
    #pragma unroll
    for (int o = 16; o > 0; o >>= 1)
        commitLocal += __shfl_xor_sync(0xffffffffu, commitLocal, o);
    __syncthreads();
    if (lane == 0) svL[wid] = commitLocal;
    __syncthreads();
    if (tid == 0) {
        float s = 0.f;
        #pragma unroll
        for (int w = 0; w < 8; w++) s += svL[w];
        atomicAdd(&g_commit, (double)s);
    }
}

// ======================================================================
// K3: perplexities + loss
// ======================================================================
__global__ void k_final(float* __restrict__ out) {
    int g = blockIdx.x;
    int tid = threadIdx.x;
    __shared__ float s1[8], s2[8];
    float c = 0.f, p = 0.f;
    for (int m = tid; m < M; m += 256) {
        float hp = g_hardcnt[g * M + m] * (1.0f / N_TOK);
        float ap = g_avgprob[g * M + m] * (1.0f / N_TOK);
        c -= hp * log2f(hp + 1e-10f);
        p -= ap * log2f(ap + 1e-10f);
    }
    #pragma unroll
    for (int o = 16; o > 0; o >>= 1) {
        c += __shfl_xor_sync(0xffffffffu, c, o);
        p += __shfl_xor_sync(0xffffffffu, p, o);
    }
    int lane = tid & 31, w = tid >> 5;
    if (lane == 0) { s1[w] = c; s2[w] = p; }
    __syncthreads();
    if (tid == 0) {
        float cc = 0.f, pp = 0.f;
        #pragma unroll
        for (int i = 0; i < 8; i++) { cc += s1[i]; pp += s2[i]; }
        out[OFF_CODE + g] = cc;
        out[OFF_PROB + g] = pp;
        if (g == 0) out[OFF_LOSS] = (float)(g_commit / 8388608.0);
    }
}

// ======================================================================
extern "C" void kernel_launch(void* const* d_in, const int* in_sizes, int n_in,
                              void* d_out, int out_size) {
    const float* x   = (const float*)d_in[0];
    const float* emb = (const float*)d_in[1];
    const float* gu  = (const float*)d_in[2];
    float* out = (float*)d_out;

    cudaFuncSetAttribute(k_gemm_mma, cudaFuncAttributeMaxDynamicSharedMemorySize,
                         SMEM_GEMM);

    k_prep     <<<256, 256>>>(emb);
    k_convert_x<<<16384, 256>>>(x);
    k_convert_e<<<1024, 256>>>(emb);
    k_gemm_mma <<<dim3(8, 128, 2), 256, SMEM_GEMM>>>();
    k_rows     <<<dim3(N_TOK / ROWS, G), 256>>>(x, emb, gu, out);
    k_final    <<<G, 256>>>(out);
}